// round 1
// baseline (speedup 1.0000x reference)
#include <cuda_runtime.h>
#include <math.h>

// Problem constants
#define V_NUM 4
#define B_SZ  2048
#define D_DIM 512
#define N_ROWS (V_NUM * B_SZ)     // 8192
#define INV_TEMP 2.0f             // 1 / 0.5

// Scratch (no allocation allowed -> device globals)
__device__ float g_xn[(size_t)N_ROWS * D_DIM];   // normalized rows, fp32
__device__ float g_rowsum[N_ROWS];               // sum_c exp(sim[r,c])

// ---------------------------------------------------------------------------
// Kernel 0: zero rowsum + output (graph replays must be deterministic)
// ---------------------------------------------------------------------------
__global__ void zero_kernel(float* __restrict__ out, int out_size) {
    int i = blockIdx.x * blockDim.x + threadIdx.x;
    if (i < N_ROWS) g_rowsum[i] = 0.0f;
    if (i < out_size) out[i] = 0.0f;
}

// ---------------------------------------------------------------------------
// Kernel 1: row L2-normalize.  One block (128 threads) per row; each thread
// owns one float4 (128 * 4 = 512 elements).
// ---------------------------------------------------------------------------
__global__ void normalize_kernel(const float* __restrict__ x) {
    int row = blockIdx.x;
    int t = threadIdx.x;
    const float4* xr = (const float4*)(x + (size_t)row * D_DIM);
    float4 v = xr[t];
    float ss = v.x * v.x + v.y * v.y + v.z * v.z + v.w * v.w;
    #pragma unroll
    for (int o = 16; o > 0; o >>= 1) ss += __shfl_xor_sync(0xFFFFFFFFu, ss, o);
    __shared__ float ws[4];
    if ((t & 31) == 0) ws[t >> 5] = ss;
    __syncthreads();
    float tot = ws[0] + ws[1] + ws[2] + ws[3];
    float norm = sqrtf(tot);
    float inv = 1.0f / fmaxf(norm, 1e-8f);
    float4 o4 = make_float4(v.x * inv, v.y * inv, v.z * inv, v.w * inv);
    ((float4*)(g_xn + (size_t)row * D_DIM))[t] = o4;
}

// ---------------------------------------------------------------------------
// Kernel 2: fused sim = (xn @ xn^T) * INV_TEMP, exp, and row/col reduction
// into g_rowsum.  Symmetric: only tiles with bx >= by are computed; an
// off-diagonal tile contributes its exp-sums to BOTH its row block and its
// column block (columns are rows by symmetry).
//
// Tile: 128x128, TK=16, 256 threads, 8x8 accumulators per thread.
// ---------------------------------------------------------------------------
#define TM 128
#define TN 128
#define TK 16

__global__ __launch_bounds__(256, 2)
void simexp_kernel() {
    int bx = blockIdx.x, by = blockIdx.y;
    if (bx < by) return;                       // lower triangle: skip
    const int rowBase = by * TM;
    const int colBase = bx * TN;

    __shared__ float As[TK][TM + 4];
    __shared__ float Bs[TK][TN + 4];

    const int tid = threadIdx.x;
    const int tx = tid & 15;                   // 0..15 (col group)
    const int ty = tid >> 4;                   // 0..15 (row group)

    float acc[8][8];
    #pragma unroll
    for (int i = 0; i < 8; i++)
        #pragma unroll
        for (int j = 0; j < 8; j++) acc[i][j] = 0.0f;

    const int lr = tid >> 2;                   // 0..63
    const int lc = (tid & 3) << 2;             // 0,4,8,12

    for (int k0 = 0; k0 < D_DIM; k0 += TK) {
        #pragma unroll
        for (int rr = 0; rr < TM; rr += 64) {
            float4 av = *(const float4*)&g_xn[(size_t)(rowBase + lr + rr) * D_DIM + k0 + lc];
            As[lc + 0][lr + rr] = av.x;
            As[lc + 1][lr + rr] = av.y;
            As[lc + 2][lr + rr] = av.z;
            As[lc + 3][lr + rr] = av.w;
            float4 bv = *(const float4*)&g_xn[(size_t)(colBase + lr + rr) * D_DIM + k0 + lc];
            Bs[lc + 0][lr + rr] = bv.x;
            Bs[lc + 1][lr + rr] = bv.y;
            Bs[lc + 2][lr + rr] = bv.z;
            Bs[lc + 3][lr + rr] = bv.w;
        }
        __syncthreads();

        #pragma unroll
        for (int kk = 0; kk < TK; kk++) {
            float a[8], b[8];
            *(float4*)(a)     = *(const float4*)&As[kk][ty * 8];
            *(float4*)(a + 4) = *(const float4*)&As[kk][ty * 8 + 4];
            *(float4*)(b)     = *(const float4*)&Bs[kk][tx * 8];
            *(float4*)(b + 4) = *(const float4*)&Bs[kk][tx * 8 + 4];
            #pragma unroll
            for (int i = 0; i < 8; i++)
                #pragma unroll
                for (int j = 0; j < 8; j++)
                    acc[i][j] = fmaf(a[i], b[j], acc[i][j]);
        }
        __syncthreads();
    }

    // Epilogue: exp + per-thread row/col partial sums (sim bounded in [-2,2],
    // exp needs no max-shift).
    float rowp[8], colp[8];
    #pragma unroll
    for (int i = 0; i < 8; i++) { rowp[i] = 0.0f; colp[i] = 0.0f; }
    #pragma unroll
    for (int i = 0; i < 8; i++) {
        #pragma unroll
        for (int j = 0; j < 8; j++) {
            float ev = __expf(acc[i][j] * INV_TEMP);
            rowp[i] += ev;
            colp[j] += ev;
        }
    }

    // Row reduction across the 16 tx groups (reuse As as scratch).
    #pragma unroll
    for (int i = 0; i < 8; i++) As[tx][ty * 8 + i] = rowp[i];
    __syncthreads();
    if (tid < TM) {
        float s = 0.0f;
        #pragma unroll
        for (int x = 0; x < 16; x++) s += As[x][tid];
        atomicAdd(&g_rowsum[rowBase + tid], s);
    }

    if (bx != by) {
        // Column reduction across the 16 ty groups -> rowsum of column block.
        __syncthreads();
        #pragma unroll
        for (int j = 0; j < 8; j++) As[ty][tx * 8 + j] = colp[j];
        __syncthreads();
        if (tid < TN) {
            float s = 0.0f;
            #pragma unroll
            for (int x = 0; x < 16; x++) s += As[x][tid];
            atomicAdd(&g_rowsum[colBase + tid], s);
        }
    }
}

// ---------------------------------------------------------------------------
// Kernel 3: per-anchor loss.  One warp per anchor row r = i*B + b.
//   pos_j  = dot(xn[r], xn[j*B+b]) * INV_TEMP          (j = 0..V-1)
//   S      = rowsum[r] - sum_j exp(pos_j)              (negatives-only sum)
//   loss  += sum_{j != i} log1p(S * exp(-pos_j)) / B
// ---------------------------------------------------------------------------
__global__ void loss_kernel(float* __restrict__ out) {
    int warp = (blockIdx.x * blockDim.x + threadIdx.x) >> 5;
    int lane = threadIdx.x & 31;
    if (warp >= N_ROWS) return;
    const int r = warp;
    const int iview = r / B_SZ;
    const int b = r % B_SZ;

    const float4* xr = (const float4*)(g_xn + (size_t)r * D_DIM);
    float4 a[4];
    #pragma unroll
    for (int q = 0; q < 4; q++) a[q] = xr[lane + q * 32];

    float pos[V_NUM];
    #pragma unroll
    for (int j = 0; j < V_NUM; j++) {
        const float4* xc = (const float4*)(g_xn + (size_t)(j * B_SZ + b) * D_DIM);
        float d = 0.0f;
        #pragma unroll
        for (int q = 0; q < 4; q++) {
            float4 w = xc[lane + q * 32];
            d = fmaf(a[q].x, w.x, d);
            d = fmaf(a[q].y, w.y, d);
            d = fmaf(a[q].z, w.z, d);
            d = fmaf(a[q].w, w.w, d);
        }
        #pragma unroll
        for (int o = 16; o > 0; o >>= 1) d += __shfl_xor_sync(0xFFFFFFFFu, d, o);
        pos[j] = d * INV_TEMP;
    }

    if (lane == 0) {
        float S = g_rowsum[r];
        #pragma unroll
        for (int j = 0; j < V_NUM; j++) S -= __expf(pos[j]);
        float loss = 0.0f;
        #pragma unroll
        for (int j = 0; j < V_NUM; j++) {
            if (j != iview)
                loss += log1pf(S * __expf(-pos[j]));
        }
        atomicAdd(out, loss * (1.0f / (float)B_SZ));
    }
}

// ---------------------------------------------------------------------------
extern "C" void kernel_launch(void* const* d_in, const int* in_sizes, int n_in,
                              void* d_out, int out_size) {
    const float* x = (const float*)d_in[0];
    float* out = (float*)d_out;

    zero_kernel<<<(N_ROWS + 255) / 256, 256>>>(out, out_size);
    normalize_kernel<<<N_ROWS, 128>>>(x);
    dim3 grid(N_ROWS / TN, N_ROWS / TM);
    simexp_kernel<<<grid, 256>>>();
    loss_kernel<<<(N_ROWS * 32) / 256, 256>>>(out);
}

// round 3
// speedup vs baseline: 7.0838x; 7.0838x over previous
#include <cuda_runtime.h>
#include <cuda_bf16.h>
#include <math.h>
#include <stdint.h>

#define V_NUM 4
#define B_SZ  2048
#define D_DIM 512
#define N_ROWS 8192

// Scratch (no allocation allowed -> device globals)
__device__ __nv_bfloat16 g_xn[(size_t)N_ROWS * D_DIM];   // normalized rows, bf16
__device__ float g_rowsum[N_ROWS];                       // sum_c exp(sim[r,c])
__device__ float g_pos[V_NUM * V_NUM * B_SZ];            // sim(i*B+b, j*B+b), i<=j

// ---------------------------------------------------------------------------
__global__ void zero_kernel(float* __restrict__ out) {
    int i = blockIdx.x * blockDim.x + threadIdx.x;
    if (i < N_ROWS) g_rowsum[i] = 0.0f;
    if (i == 0) out[0] = 0.0f;
}

// ---------------------------------------------------------------------------
// Row L2-normalize -> bf16.  One 128-thread block per row.
// ---------------------------------------------------------------------------
__global__ void normalize_kernel(const float* __restrict__ x) {
    int row = blockIdx.x;
    int t = threadIdx.x;
    float4 v = ((const float4*)(x + (size_t)row * D_DIM))[t];
    float ss = fmaf(v.x, v.x, fmaf(v.y, v.y, fmaf(v.z, v.z, v.w * v.w)));
    #pragma unroll
    for (int o = 16; o > 0; o >>= 1) ss += __shfl_xor_sync(0xFFFFFFFFu, ss, o);
    __shared__ float ws[4];
    if ((t & 31) == 0) ws[t >> 5] = ss;
    __syncthreads();
    float tot = ws[0] + ws[1] + ws[2] + ws[3];
    float inv = 1.0f / fmaxf(sqrtf(tot), 1e-8f);
    __nv_bfloat162* dst = (__nv_bfloat162*)(g_xn + (size_t)row * D_DIM);
    dst[2 * t]     = __floats2bfloat162_rn(v.x * inv, v.y * inv);
    dst[2 * t + 1] = __floats2bfloat162_rn(v.z * inv, v.w * inv);
}

// ---------------------------------------------------------------------------
// Tensor-core fused kernel: sim = 2 * (xn @ xn^T) on bf16 HMMA, exp epilogue,
// row/col exp-sums (symmetry: only bx >= by tiles computed, off-diag tiles
// feed both row and col sums), positives extracted from tile diagonals.
//
// Tile 128x128, Kc=64, 8 warps (4x2), per warp 32x64 (2 x 8 m16n8 mma tiles).
// SW128-swizzled smem, cp.async double-buffered.
// ---------------------------------------------------------------------------
__device__ __forceinline__ void cp16(uint32_t s, const void* g) {
    asm volatile("cp.async.cg.shared.global [%0], [%1], 16;\n" :: "r"(s), "l"(g));
}

__global__ __launch_bounds__(256, 2)
void simexp_kernel() {
    const int bx = blockIdx.x, by = blockIdx.y;
    if (bx < by) return;
    extern __shared__ char smem[];
    const uint32_t smemU = (uint32_t)__cvta_generic_to_shared(smem);
    const int tid = threadIdx.x;
    const int lane = tid & 31;
    const int wid = tid >> 5;
    const int wm = wid >> 1;            // 0..3: 32-row band
    const int wn = wid & 1;             // 0..1: 64-col band
    const int rowBase = by << 7, colBase = bx << 7;

    float* s_rsum = (float*)(smem + 65536);
    float* s_csum = s_rsum + 128;
    if (tid < 128) { s_rsum[tid] = 0.0f; s_csum[tid] = 0.0f; }

    float acc[2][8][4];
    #pragma unroll
    for (int mi = 0; mi < 2; mi++)
        #pragma unroll
        for (int ni = 0; ni < 8; ni++)
            #pragma unroll
            for (int e = 0; e < 4; e++) acc[mi][ni][e] = 0.0f;

    // --- global -> smem loaders (cp.async, SW128 swizzle: chunk' = c ^ (r&7))
    const int lr = tid >> 3;                          // 0..31
    const int lc = tid & 7;                           // 16B chunk in row
    const uint32_t swzCol = (uint32_t)((lc ^ (lr & 7)) << 4);
    const char* gbase = (const char*)g_xn;

    auto load_iter = [&](int it, int buf) {
        uint32_t sbase = smemU + buf * 32768;
        #pragma unroll
        for (int tp = 0; tp < 2; tp++) {
            const int rb = tp ? colBase : rowBase;
            const uint32_t sb = sbase + tp * 16384;
            #pragma unroll
            for (int u = 0; u < 4; u++) {
                int r = lr + 32 * u;
                cp16(sb + (uint32_t)(r * 128) + swzCol,
                     gbase + (size_t)(rb + r) * (D_DIM * 2) + it * 128 + lc * 16);
            }
        }
    };

    // --- fragment address components (constant across k-iters)
    const int rA0 = wm * 32 + (lane & 15);
    const int nB0 = wn * 64 + ((lane >> 4) << 3) + (lane & 7);
    const int laneSw = lane & 7;

    auto compute_iter = [&](int buf) {
        const uint32_t sA = smemU + buf * 32768;
        const uint32_t sB = sA + 16384;
        #pragma unroll
        for (int kk = 0; kk < 4; kk++) {
            uint32_t a[2][4];
            const uint32_t chA = (uint32_t)(((kk * 2 + (lane >> 4)) ^ laneSw) << 4);
            #pragma unroll
            for (int m2 = 0; m2 < 2; m2++) {
                uint32_t addr = sA + (uint32_t)((rA0 + m2 * 16) * 128) + chA;
                asm volatile("ldmatrix.sync.aligned.m8n8.x4.shared.b16 {%0,%1,%2,%3}, [%4];"
                    : "=r"(a[m2][0]), "=r"(a[m2][1]), "=r"(a[m2][2]), "=r"(a[m2][3])
                    : "r"(addr));
            }
            uint32_t b[4][4];
            const uint32_t chB = (uint32_t)(((kk * 2 + ((lane >> 3) & 1)) ^ laneSw) << 4);
            #pragma unroll
            for (int g = 0; g < 4; g++) {
                uint32_t addr = sB + (uint32_t)((nB0 + g * 16) * 128) + chB;
                asm volatile("ldmatrix.sync.aligned.m8n8.x4.shared.b16 {%0,%1,%2,%3}, [%4];"
                    : "=r"(b[g][0]), "=r"(b[g][1]), "=r"(b[g][2]), "=r"(b[g][3])
                    : "r"(addr));
            }
            #pragma unroll
            for (int mi = 0; mi < 2; mi++)
                #pragma unroll
                for (int ni = 0; ni < 8; ni++) {
                    uint32_t b0 = b[ni >> 1][(ni & 1) * 2];
                    uint32_t b1 = b[ni >> 1][(ni & 1) * 2 + 1];
                    asm volatile(
                        "mma.sync.aligned.m16n8k16.row.col.f32.bf16.bf16.f32 "
                        "{%0,%1,%2,%3}, {%4,%5,%6,%7}, {%8,%9}, {%0,%1,%2,%3};"
                        : "+f"(acc[mi][ni][0]), "+f"(acc[mi][ni][1]),
                          "+f"(acc[mi][ni][2]), "+f"(acc[mi][ni][3])
                        : "r"(a[mi][0]), "r"(a[mi][1]), "r"(a[mi][2]), "r"(a[mi][3]),
                          "r"(b0), "r"(b1));
                }
        }
    };

    // --- mainloop: 8 k-iterations of 64, double buffered
    load_iter(0, 0);
    asm volatile("cp.async.commit_group;\n" ::);
    #pragma unroll 1
    for (int it = 0; it < 8; it++) {
        if (it < 7) {
            load_iter(it + 1, (it + 1) & 1);
            asm volatile("cp.async.commit_group;\n" ::);
            asm volatile("cp.async.wait_group 1;\n" ::);
        } else {
            asm volatile("cp.async.wait_group 0;\n" ::);
        }
        __syncthreads();
        compute_iter(it & 1);
        __syncthreads();
    }

    // --- epilogue: exp, row/col partial sums, positive extraction
    const bool posTile = ((bx - by) & 15) == 0;
    float rowp[2][2] = {{0.f, 0.f}, {0.f, 0.f}};
    float colp[8][2];
    #pragma unroll
    for (int ni = 0; ni < 8; ni++) { colp[ni][0] = 0.f; colp[ni][1] = 0.f; }

    #pragma unroll
    for (int mi = 0; mi < 2; mi++)
        #pragma unroll
        for (int ni = 0; ni < 8; ni++)
            #pragma unroll
            for (int e = 0; e < 4; e++) {
                float sim2 = acc[mi][ni][e] * 2.0f;
                float ev = __expf(sim2);
                rowp[mi][e >> 1] += ev;
                colp[ni][e & 1] += ev;
                if (posTile) {
                    int rl = wm * 32 + mi * 16 + (e >> 1) * 8 + (lane >> 2);
                    int cl = wn * 64 + ni * 8 + (lane & 3) * 2 + (e & 1);
                    if (rl == cl) {
                        int gr = rowBase + rl, gc = colBase + cl;
                        g_pos[((gr >> 11) * V_NUM + (gc >> 11)) * B_SZ + (gr & 2047)] = sim2;
                    }
                }
            }

    // row sums: reduce over the 4 lanes of each quad
    #pragma unroll
    for (int mi = 0; mi < 2; mi++)
        #pragma unroll
        for (int rh = 0; rh < 2; rh++) {
            float s = rowp[mi][rh];
            s += __shfl_xor_sync(0xFFFFFFFFu, s, 1);
            s += __shfl_xor_sync(0xFFFFFFFFu, s, 2);
            if ((lane & 3) == 0)
                atomicAdd(&s_rsum[wm * 32 + mi * 16 + rh * 8 + (lane >> 2)], s);
        }
    // col sums: reduce over the 8 lanes sharing (lane & 3)
    #pragma unroll
    for (int ni = 0; ni < 8; ni++)
        #pragma unroll
        for (int e01 = 0; e01 < 2; e01++) {
            float s = colp[ni][e01];
            s += __shfl_xor_sync(0xFFFFFFFFu, s, 4);
            s += __shfl_xor_sync(0xFFFFFFFFu, s, 8);
            s += __shfl_xor_sync(0xFFFFFFFFu, s, 16);
            if (lane < 4)
                atomicAdd(&s_csum[wn * 64 + ni * 8 + lane * 2 + e01], s);
        }
    __syncthreads();
    if (tid < 128) {
        atomicAdd(&g_rowsum[rowBase + tid], s_rsum[tid]);
    } else if (bx != by) {
        atomicAdd(&g_rowsum[colBase + tid - 128], s_csum[tid - 128]);
    }
}

// ---------------------------------------------------------------------------
// Per-anchor loss from rowsum + extracted positives.
// ---------------------------------------------------------------------------
__global__ void loss_kernel(float* __restrict__ out) {
    int r = blockIdx.x * blockDim.x + threadIdx.x;
    int i = r >> 11, b = r & 2047;
    float p[V_NUM];
    #pragma unroll
    for (int j = 0; j < V_NUM; j++) {
        int lo = i < j ? i : j;
        int hi = i < j ? j : i;
        p[j] = g_pos[(lo * V_NUM + hi) * B_SZ + b];
    }
    float S = g_rowsum[r];
    #pragma unroll
    for (int j = 0; j < V_NUM; j++) S -= __expf(p[j]);
    float L = 0.0f;
    #pragma unroll
    for (int j = 0; j < V_NUM; j++)
        if (j != i) L += log1pf(S * __expf(-p[j]));
    L *= (1.0f / (float)B_SZ);
    #pragma unroll
    for (int o = 16; o > 0; o >>= 1) L += __shfl_xor_sync(0xFFFFFFFFu, L, o);
    __shared__ float ws[8];
    if ((threadIdx.x & 31) == 0) ws[threadIdx.x >> 5] = L;
    __syncthreads();
    if (threadIdx.x == 0) {
        float s = 0.0f;
        #pragma unroll
        for (int w = 0; w < 8; w++) s += ws[w];
        atomicAdd(out, s);
    }
}

// ---------------------------------------------------------------------------
#define SIMEXP_SMEM (2 * 32768 + 1024)

extern "C" void kernel_launch(void* const* d_in, const int* in_sizes, int n_in,
                              void* d_out, int out_size) {
    const float* x = (const float*)d_in[0];
    float* out = (float*)d_out;

    cudaFuncSetAttribute(simexp_kernel,
                         cudaFuncAttributeMaxDynamicSharedMemorySize, SIMEXP_SMEM);

    zero_kernel<<<(N_ROWS + 255) / 256, 256>>>(out);
    normalize_kernel<<<N_ROWS, 128>>>(x);
    dim3 grid(N_ROWS / 128, N_ROWS / 128);
    simexp_kernel<<<grid, 256, SIMEXP_SMEM>>>();
    loss_kernel<<<N_ROWS / 256, 256>>>(out);
}